// round 4
// baseline (speedup 1.0000x reference)
#include <cuda_runtime.h>

#define DD 64
#define NMAX 100000
#define EMAX 1200000

// Scratch (allocation-free rule: __device__ globals). 16B-aligned for vector access.
__device__ __align__(16) float  g_deg[NMAX];
__device__ __align__(16) float  g_dis[NMAX];
__device__ __align__(16) int    g_cnt[NMAX];
__device__ __align__(16) int    g_row[NMAX + 1];
__device__ __align__(16) int    g_cur[NMAX];
__device__ __align__(16) float2 g_pair[EMAX];      // (src as int bits, weight), bucketed by dst
__device__ __align__(16) float  g_hs [NMAX * DD];  // dis[i] * (X@W)[i]
__device__ __align__(16) float  g_x1 [NMAX * DD];  // layer-1 output

// ---------------------------------------------------------------------------
// init: cnt = 0, deg = 1 (self-loop weight)
__global__ void init_kernel(int n) {
    int i = blockIdx.x * blockDim.x + threadIdx.x;
    if (i < n) { g_cnt[i] = 0; g_deg[i] = 1.0f; }
}

// count in-degree + weighted degree.  edge_index is INT32: src = ei[e], dst = ei[E+e].
__global__ void count_kernel(const int* __restrict__ ei,
                             const float* __restrict__ ew, int E) {
    int e = blockIdx.x * blockDim.x + threadIdx.x;
    if (e < E) {
        int d = ei[E + e];
        atomicAdd(&g_cnt[d], 1);
        atomicAdd(&g_deg[d], ew[e]);
    }
}

// single-block exclusive scan of g_cnt -> g_row, g_cur; also dis = rsqrt(deg)
__global__ __launch_bounds__(1024) void scan_dis_kernel(int n) {
    __shared__ int ssum[1024];
    int t = threadIdx.x;
    int chunk = (n + 1023) >> 10;
    int beg = t * chunk;
    int end = min(n, beg + chunk);
    int s = 0;
    for (int i = beg; i < end; i++) s += g_cnt[i];
    ssum[t] = s;
    __syncthreads();
    if (t == 0) {
        int acc = 0;
        for (int i = 0; i < 1024; i++) { int v = ssum[i]; ssum[i] = acc; acc += v; }
        g_row[n] = acc;
    }
    __syncthreads();
    int acc = ssum[t];
    for (int i = beg; i < end; i++) {
        int c = g_cnt[i];
        g_row[i] = acc;
        g_cur[i] = acc;
        acc += c;
        g_dis[i] = rsqrtf(g_deg[i]);
    }
}

// bucket edges by dst: g_pair[slot] = (src, w)
__global__ void fill_kernel(const int* __restrict__ ei,
                            const float* __restrict__ ew, int E) {
    int e = blockIdx.x * blockDim.x + threadIdx.x;
    if (e < E) {
        int s = ei[e];
        int d = ei[E + e];
        int p = atomicAdd(&g_cur[d], 1);
        g_pair[p] = make_float2(__int_as_float(s), ew[e]);
    }
}

// ---------------------------------------------------------------------------
// GEMM: hs = dis[row] * (X @ W).  One block = 64 rows, 256 threads, 4x4 tiles.
// Inner loop k-unrolled by 4 with float4 loads on both operands.
__global__ __launch_bounds__(256) void gemm_hs_kernel(
    const float* __restrict__ Xin, const float* __restrict__ W, int n, int src_sel)
{
    __shared__ float sW[DD * DD];
    __shared__ float sX[DD * DD];

    const float* X = src_sel ? (const float*)g_x1 : Xin;

    int t = threadIdx.x;
    int row0 = blockIdx.x * 64;

    {   // W (4096 floats) coalesced as float4
        float4* sW4 = (float4*)sW;
        const float4* W4 = (const float4*)W;
        #pragma unroll
        for (int i = 0; i < 4; i++) sW4[t + i * 256] = W4[t + i * 256];
    }
    {   // X tile, zero-pad OOB rows
        float4* sX4 = (float4*)sX;
        const float4* X4 = (const float4*)X;
        if (row0 + 64 <= n) {
            #pragma unroll
            for (int i = 0; i < 4; i++) sX4[t + i * 256] = X4[(size_t)row0 * 16 + t + i * 256];
        } else {
            #pragma unroll
            for (int i = 0; i < 4; i++) {
                int idx = t + i * 256;
                int r = idx >> 4;
                float4 v = make_float4(0.f, 0.f, 0.f, 0.f);
                if (row0 + r < n) v = X4[(size_t)row0 * 16 + idx];
                sX4[idx] = v;
            }
        }
    }
    __syncthreads();

    int rg = (t >> 4) * 4;        // row base within tile
    int c0 = (t & 15) * 4;        // col base

    float a[4][4];
    #pragma unroll
    for (int i = 0; i < 4; i++)
        #pragma unroll
        for (int j = 0; j < 4; j++) a[i][j] = 0.f;

    #pragma unroll
    for (int k = 0; k < 64; k += 4) {
        float4 w0 = *(const float4*)(sW + (k + 0) * 64 + c0);
        float4 w1 = *(const float4*)(sW + (k + 1) * 64 + c0);
        float4 w2 = *(const float4*)(sW + (k + 2) * 64 + c0);
        float4 w3 = *(const float4*)(sW + (k + 3) * 64 + c0);
        #pragma unroll
        for (int i = 0; i < 4; i++) {
            float4 xk = *(const float4*)(sX + (rg + i) * 64 + k);
            a[i][0] = fmaf(xk.x, w0.x, a[i][0]);
            a[i][1] = fmaf(xk.x, w0.y, a[i][1]);
            a[i][2] = fmaf(xk.x, w0.z, a[i][2]);
            a[i][3] = fmaf(xk.x, w0.w, a[i][3]);
            a[i][0] = fmaf(xk.y, w1.x, a[i][0]);
            a[i][1] = fmaf(xk.y, w1.y, a[i][1]);
            a[i][2] = fmaf(xk.y, w1.z, a[i][2]);
            a[i][3] = fmaf(xk.y, w1.w, a[i][3]);
            a[i][0] = fmaf(xk.z, w2.x, a[i][0]);
            a[i][1] = fmaf(xk.z, w2.y, a[i][1]);
            a[i][2] = fmaf(xk.z, w2.z, a[i][2]);
            a[i][3] = fmaf(xk.z, w2.w, a[i][3]);
            a[i][0] = fmaf(xk.w, w3.x, a[i][0]);
            a[i][1] = fmaf(xk.w, w3.y, a[i][1]);
            a[i][2] = fmaf(xk.w, w3.z, a[i][2]);
            a[i][3] = fmaf(xk.w, w3.w, a[i][3]);
        }
    }

    float4* hp = (float4*)g_hs;
    #pragma unroll
    for (int i = 0; i < 4; i++) {
        int r = row0 + rg + i;
        if (r < n) {
            float ds = g_dis[r];
            hp[(size_t)r * 16 + (c0 >> 2)] =
                make_float4(a[i][0] * ds, a[i][1] * ds, a[i][2] * ds, a[i][3] * ds);
        }
    }
}

// ---------------------------------------------------------------------------
// Gather-aggregate: ONE WARP per node, each lane owns one float2 column chunk.
//   acc = hs[d] (self-loop); acc += w_e * hs[src_e]; r = relu(dis[d]*acc + b)
//   mode 0: x1 = r          mode 1: out = 0.5*(x1 + r)
// Edge loop unrolled x2 for MLP; pair loads are warp-uniform (broadcast).
__global__ __launch_bounds__(256) void gather_kernel(
    const float* __restrict__ b, float* __restrict__ out, int n, int mode)
{
    int d = (blockIdx.x * blockDim.x + threadIdx.x) >> 5;
    if (d >= n) return;
    int lane = threadIdx.x & 31;

    const float2* __restrict__ hs2 = (const float2*)g_hs;
    size_t oi = (size_t)d * 32 + lane;

    float2 acc = hs2[oi];
    int beg = g_row[d];
    int end = g_row[d + 1];

    int i = beg;
    for (; i + 2 <= end; i += 2) {
        float2 p0 = g_pair[i];
        float2 p1 = g_pair[i + 1];
        int s0 = __float_as_int(p0.x);
        int s1 = __float_as_int(p1.x);
        float2 v0 = hs2[(size_t)s0 * 32 + lane];
        float2 v1 = hs2[(size_t)s1 * 32 + lane];
        acc.x = fmaf(p0.y, v0.x, acc.x);
        acc.y = fmaf(p0.y, v0.y, acc.y);
        acc.x = fmaf(p1.y, v1.x, acc.x);
        acc.y = fmaf(p1.y, v1.y, acc.y);
    }
    if (i < end) {
        float2 p0 = g_pair[i];
        int s0 = __float_as_int(p0.x);
        float2 v0 = hs2[(size_t)s0 * 32 + lane];
        acc.x = fmaf(p0.y, v0.x, acc.x);
        acc.y = fmaf(p0.y, v0.y, acc.y);
    }

    float ds = g_dis[d];
    float2 bb = ((const float2*)b)[lane];
    float2 r;
    r.x = fmaxf(fmaf(ds, acc.x, bb.x), 0.f);
    r.y = fmaxf(fmaf(ds, acc.y, bb.y), 0.f);

    if (mode == 0) {
        ((float2*)g_x1)[oi] = r;
    } else {
        float2 x1v = ((const float2*)g_x1)[oi];
        r.x = 0.5f * (x1v.x + r.x);
        r.y = 0.5f * (x1v.y + r.y);
        ((float2*)out)[oi] = r;
    }
}

// ---------------------------------------------------------------------------
extern "C" void kernel_launch(void* const* d_in, const int* in_sizes, int n_in,
                              void* d_out, int out_size) {
    const float* x  = (const float*)d_in[0];
    const int*   ei = (const int*)d_in[1];      // int32 (JAX default x64-disabled)
    const float* ew = (const float*)d_in[2];
    const float* W1 = (const float*)d_in[3];
    const float* b1 = (const float*)d_in[4];
    const float* W2 = (const float*)d_in[5];
    const float* b2 = (const float*)d_in[6];
    float* out = (float*)d_out;

    int n = in_sizes[0] / DD;      // 100000
    int E = in_sizes[2];           // 1200000

    int nb_n   = (n + 255) / 256;
    int nb_e   = (E + 255) / 256;
    int nb_gat = (int)(((long long)n * 32 + 255) / 256);
    int nb_g   = (n + 63) / 64;

    // CSR + degree (shared across both layers)
    init_kernel<<<nb_n, 256>>>(n);                      // 1
    count_kernel<<<nb_e, 256>>>(ei, ew, E);             // 2
    scan_dis_kernel<<<1, 1024>>>(n);                    // 3 (scan + dis fused)
    fill_kernel<<<nb_e, 256>>>(ei, ew, E);              // 4

    // Layer 1
    gemm_hs_kernel<<<nb_g, 256>>>(x, W1, n, 0);         // 5
    gather_kernel<<<nb_gat, 256>>>(b1, out, n, 0);      // 6  <- ncu -s 5 lands here
    // Layer 2
    gemm_hs_kernel<<<nb_g, 256>>>(x, W2, n, 1);         // 7
    gather_kernel<<<nb_gat, 256>>>(b2, out, n, 1);      // 8
}

// round 5
// speedup vs baseline: 1.0015x; 1.0015x over previous
#include <cuda_runtime.h>

#define DD 64
#define NMAX 100000
#define EMAX 1200000

// Scratch (allocation-free rule: __device__ globals). 16B-aligned for vector access.
__device__ __align__(16) float  g_deg[NMAX];
__device__ __align__(16) float  g_dis[NMAX];
__device__ __align__(16) int    g_cnt[NMAX];
__device__ __align__(16) int    g_row[NMAX + 1];
__device__ __align__(16) int    g_cur[NMAX];
__device__ __align__(16) float2 g_pair[EMAX];      // (src as int bits, weight), bucketed by dst
__device__ __align__(16) float  g_hs [NMAX * DD];  // dis[i] * (X@W)[i]
__device__ __align__(16) float  g_x1 [NMAX * DD];  // layer-1 output

// ---------------------------------------------------------------------------
// init: cnt = 0, deg = 1 (self-loop weight)
__global__ void init_kernel(int n) {
    int i = blockIdx.x * blockDim.x + threadIdx.x;
    if (i < n) { g_cnt[i] = 0; g_deg[i] = 1.0f; }
}

// count in-degree + weighted degree.  edge_index is INT32: src = ei[e], dst = ei[E+e].
__global__ void count_kernel(const int* __restrict__ ei,
                             const float* __restrict__ ew, int E) {
    int e = blockIdx.x * blockDim.x + threadIdx.x;
    if (e < E) {
        int d = ei[E + e];
        atomicAdd(&g_cnt[d], 1);
        atomicAdd(&g_deg[d], ew[e]);
    }
}

// single-block exclusive scan of g_cnt -> g_row, g_cur; also dis = rsqrt(deg)
__global__ __launch_bounds__(1024) void scan_dis_kernel(int n) {
    __shared__ int ssum[1024];
    int t = threadIdx.x;
    int chunk = (n + 1023) >> 10;
    int beg = t * chunk;
    int end = min(n, beg + chunk);
    int s = 0;
    for (int i = beg; i < end; i++) s += g_cnt[i];
    ssum[t] = s;
    __syncthreads();
    if (t == 0) {
        int acc = 0;
        for (int i = 0; i < 1024; i++) { int v = ssum[i]; ssum[i] = acc; acc += v; }
        g_row[n] = acc;
    }
    __syncthreads();
    int acc = ssum[t];
    for (int i = beg; i < end; i++) {
        int c = g_cnt[i];
        g_row[i] = acc;
        g_cur[i] = acc;
        acc += c;
        g_dis[i] = rsqrtf(g_deg[i]);
    }
}

// bucket edges by dst: g_pair[slot] = (src, w)
__global__ void fill_kernel(const int* __restrict__ ei,
                            const float* __restrict__ ew, int E) {
    int e = blockIdx.x * blockDim.x + threadIdx.x;
    if (e < E) {
        int s = ei[e];
        int d = ei[E + e];
        int p = atomicAdd(&g_cur[d], 1);
        g_pair[p] = make_float2(__int_as_float(s), ew[e]);
    }
}

// ---------------------------------------------------------------------------
// GEMM: hs = dis[row] * (X @ W).  One block = 64 rows, 256 threads, 4x4 tiles.
// Inner loop k-unrolled by 4 with float4 loads on both operands.
__global__ __launch_bounds__(256) void gemm_hs_kernel(
    const float* __restrict__ Xin, const float* __restrict__ W, int n, int src_sel)
{
    __shared__ float sW[DD * DD];
    __shared__ float sX[DD * DD];

    const float* X = src_sel ? (const float*)g_x1 : Xin;

    int t = threadIdx.x;
    int row0 = blockIdx.x * 64;

    {   // W (4096 floats) coalesced as float4
        float4* sW4 = (float4*)sW;
        const float4* W4 = (const float4*)W;
        #pragma unroll
        for (int i = 0; i < 4; i++) sW4[t + i * 256] = W4[t + i * 256];
    }
    {   // X tile, zero-pad OOB rows
        float4* sX4 = (float4*)sX;
        const float4* X4 = (const float4*)X;
        if (row0 + 64 <= n) {
            #pragma unroll
            for (int i = 0; i < 4; i++) sX4[t + i * 256] = X4[(size_t)row0 * 16 + t + i * 256];
        } else {
            #pragma unroll
            for (int i = 0; i < 4; i++) {
                int idx = t + i * 256;
                int r = idx >> 4;
                float4 v = make_float4(0.f, 0.f, 0.f, 0.f);
                if (row0 + r < n) v = X4[(size_t)row0 * 16 + idx];
                sX4[idx] = v;
            }
        }
    }
    __syncthreads();

    int rg = (t >> 4) * 4;        // row base within tile
    int c0 = (t & 15) * 4;        // col base

    float a[4][4];
    #pragma unroll
    for (int i = 0; i < 4; i++)
        #pragma unroll
        for (int j = 0; j < 4; j++) a[i][j] = 0.f;

    #pragma unroll
    for (int k = 0; k < 64; k += 4) {
        float4 w0 = *(const float4*)(sW + (k + 0) * 64 + c0);
        float4 w1 = *(const float4*)(sW + (k + 1) * 64 + c0);
        float4 w2 = *(const float4*)(sW + (k + 2) * 64 + c0);
        float4 w3 = *(const float4*)(sW + (k + 3) * 64 + c0);
        #pragma unroll
        for (int i = 0; i < 4; i++) {
            float4 xk = *(const float4*)(sX + (rg + i) * 64 + k);
            a[i][0] = fmaf(xk.x, w0.x, a[i][0]);
            a[i][1] = fmaf(xk.x, w0.y, a[i][1]);
            a[i][2] = fmaf(xk.x, w0.z, a[i][2]);
            a[i][3] = fmaf(xk.x, w0.w, a[i][3]);
            a[i][0] = fmaf(xk.y, w1.x, a[i][0]);
            a[i][1] = fmaf(xk.y, w1.y, a[i][1]);
            a[i][2] = fmaf(xk.y, w1.z, a[i][2]);
            a[i][3] = fmaf(xk.y, w1.w, a[i][3]);
            a[i][0] = fmaf(xk.z, w2.x, a[i][0]);
            a[i][1] = fmaf(xk.z, w2.y, a[i][1]);
            a[i][2] = fmaf(xk.z, w2.z, a[i][2]);
            a[i][3] = fmaf(xk.z, w2.w, a[i][3]);
            a[i][0] = fmaf(xk.w, w3.x, a[i][0]);
            a[i][1] = fmaf(xk.w, w3.y, a[i][1]);
            a[i][2] = fmaf(xk.w, w3.z, a[i][2]);
            a[i][3] = fmaf(xk.w, w3.w, a[i][3]);
        }
    }

    float4* hp = (float4*)g_hs;
    #pragma unroll
    for (int i = 0; i < 4; i++) {
        int r = row0 + rg + i;
        if (r < n) {
            float ds = g_dis[r];
            hp[(size_t)r * 16 + (c0 >> 2)] =
                make_float4(a[i][0] * ds, a[i][1] * ds, a[i][2] * ds, a[i][3] * ds);
        }
    }
}

// ---------------------------------------------------------------------------
// Gather-aggregate: 16 threads per node, thread q owns one float4 column chunk.
// (16 lanes x 16B = one 64-float row per request batch -> 16 L1tex wavefronts
//  per edge; R4 showed 8B/lane doubles wavefronts and regresses.)
//   acc = hs[d] (self-loop); acc += w_e * hs[src_e]; r = relu(dis[d]*acc + b)
//   mode 0: x1 = r          mode 1: out = 0.5*(x1 + r)
// Edge loop unrolled x2: two independent LDG.128 in flight per lane.
__global__ __launch_bounds__(256) void gather_kernel(
    const float* __restrict__ b, float* __restrict__ out, int n, int mode)
{
    int gid = blockIdx.x * blockDim.x + threadIdx.x;
    int d = gid >> 4;
    if (d >= n) return;
    int q = gid & 15;

    const float4* __restrict__ hs4 = (const float4*)g_hs;
    size_t oi = (size_t)d * 16 + q;

    float4 acc = hs4[oi];
    int beg = g_row[d];
    int end = g_row[d + 1];

    int i = beg;
    for (; i + 2 <= end; i += 2) {
        float2 p0 = g_pair[i];
        float2 p1 = g_pair[i + 1];
        float4 v0 = hs4[(size_t)__float_as_int(p0.x) * 16 + q];
        float4 v1 = hs4[(size_t)__float_as_int(p1.x) * 16 + q];
        acc.x = fmaf(p0.y, v0.x, acc.x);
        acc.y = fmaf(p0.y, v0.y, acc.y);
        acc.z = fmaf(p0.y, v0.z, acc.z);
        acc.w = fmaf(p0.y, v0.w, acc.w);
        acc.x = fmaf(p1.y, v1.x, acc.x);
        acc.y = fmaf(p1.y, v1.y, acc.y);
        acc.z = fmaf(p1.y, v1.z, acc.z);
        acc.w = fmaf(p1.y, v1.w, acc.w);
    }
    if (i < end) {
        float2 p0 = g_pair[i];
        float4 v0 = hs4[(size_t)__float_as_int(p0.x) * 16 + q];
        acc.x = fmaf(p0.y, v0.x, acc.x);
        acc.y = fmaf(p0.y, v0.y, acc.y);
        acc.z = fmaf(p0.y, v0.z, acc.z);
        acc.w = fmaf(p0.y, v0.w, acc.w);
    }

    float ds = g_dis[d];
    float4 bb = ((const float4*)b)[q];
    float4 r;
    r.x = fmaxf(fmaf(ds, acc.x, bb.x), 0.f);
    r.y = fmaxf(fmaf(ds, acc.y, bb.y), 0.f);
    r.z = fmaxf(fmaf(ds, acc.z, bb.z), 0.f);
    r.w = fmaxf(fmaf(ds, acc.w, bb.w), 0.f);

    if (mode == 0) {
        ((float4*)g_x1)[oi] = r;
    } else {
        float4 x1v = ((const float4*)g_x1)[oi];
        r.x = 0.5f * (x1v.x + r.x);
        r.y = 0.5f * (x1v.y + r.y);
        r.z = 0.5f * (x1v.z + r.z);
        r.w = 0.5f * (x1v.w + r.w);
        ((float4*)out)[oi] = r;
    }
}

// ---------------------------------------------------------------------------
extern "C" void kernel_launch(void* const* d_in, const int* in_sizes, int n_in,
                              void* d_out, int out_size) {
    const float* x  = (const float*)d_in[0];
    const int*   ei = (const int*)d_in[1];      // int32 (JAX default x64-disabled)
    const float* ew = (const float*)d_in[2];
    const float* W1 = (const float*)d_in[3];
    const float* b1 = (const float*)d_in[4];
    const float* W2 = (const float*)d_in[5];
    const float* b2 = (const float*)d_in[6];
    float* out = (float*)d_out;

    int n = in_sizes[0] / DD;      // 100000
    int E = in_sizes[2];           // 1200000

    int nb_n   = (n + 255) / 256;
    int nb_e   = (E + 255) / 256;
    int nb_gat = (int)(((long long)n * 16 + 255) / 256);
    int nb_g   = (n + 63) / 64;

    // CSR + degree (shared across both layers)
    init_kernel<<<nb_n, 256>>>(n);                      // 1
    count_kernel<<<nb_e, 256>>>(ei, ew, E);             // 2
    scan_dis_kernel<<<1, 1024>>>(n);                    // 3 (scan + dis fused)
    fill_kernel<<<nb_e, 256>>>(ei, ew, E);              // 4

    // Layer 1
    gemm_hs_kernel<<<nb_g, 256>>>(x, W1, n, 0);         // 5
    gather_kernel<<<nb_gat, 256>>>(b1, out, n, 0);      // 6  <- ncu -s 5 lands here
    // Layer 2
    gemm_hs_kernel<<<nb_g, 256>>>(x, W2, n, 1);         // 7
    gather_kernel<<<nb_gat, 256>>>(b2, out, n, 1);      // 8
}

// round 6
// speedup vs baseline: 1.3627x; 1.3606x over previous
#include <cuda_runtime.h>

#define DD 64
#define NMAX 100000
#define EMAX 1200000

// Scratch (allocation-free rule: __device__ globals). 16B-aligned for float4 access.
__device__ __align__(16) float  g_deg[NMAX];
__device__ __align__(16) float  g_dis[NMAX];
__device__ __align__(16) int    g_cnt[NMAX];
__device__ __align__(16) int    g_row[NMAX + 1];
__device__ __align__(16) int    g_cur[NMAX];
__device__ __align__(16) float2 g_pair[EMAX];      // (src as int bits, weight), bucketed by dst
__device__ __align__(16) float  g_hs [NMAX * DD];  // dis[i] * (X@W)[i]
__device__ __align__(16) float  g_x1 [NMAX * DD];  // layer-1 output

// ---------------------------------------------------------------------------
// init: cnt = 0, deg = 1 (self-loop weight)
__global__ void init_kernel(int n) {
    int i = blockIdx.x * blockDim.x + threadIdx.x;
    if (i < n) { g_cnt[i] = 0; g_deg[i] = 1.0f; }
}

// count in-degree + weighted degree.  edge_index is INT32: src = ei[e], dst = ei[E+e].
__global__ void count_kernel(const int* __restrict__ ei,
                             const float* __restrict__ ew, int E) {
    int e = blockIdx.x * blockDim.x + threadIdx.x;
    if (e < E) {
        int d = ei[E + e];
        atomicAdd(&g_cnt[d], 1);
        atomicAdd(&g_deg[d], ew[e]);
    }
}

// single-block exclusive scan of g_cnt -> g_row, g_cur; g_row[n] = E
__global__ __launch_bounds__(1024) void scan_kernel(int n) {
    __shared__ int ssum[1024];
    int t = threadIdx.x;
    int chunk = (n + 1023) >> 10;
    int beg = t * chunk;
    int end = min(n, beg + chunk);
    int s = 0;
    for (int i = beg; i < end; i++) s += g_cnt[i];
    ssum[t] = s;
    __syncthreads();
    if (t == 0) {
        int acc = 0;
        for (int i = 0; i < 1024; i++) { int v = ssum[i]; ssum[i] = acc; acc += v; }
        g_row[n] = acc;
    }
    __syncthreads();
    int acc = ssum[t];
    for (int i = beg; i < end; i++) {
        int c = g_cnt[i];
        g_row[i] = acc;
        g_cur[i] = acc;
        acc += c;
    }
}

// dis = rsqrt(deg)   (deg >= 1 always)
__global__ void dis_kernel(int n) {
    int i = blockIdx.x * blockDim.x + threadIdx.x;
    if (i < n) g_dis[i] = rsqrtf(g_deg[i]);
}

// bucket edges by dst: g_pair[slot] = (src, w)
__global__ void fill_kernel(const int* __restrict__ ei,
                            const float* __restrict__ ew, int E) {
    int e = blockIdx.x * blockDim.x + threadIdx.x;
    if (e < E) {
        int s = ei[e];
        int d = ei[E + e];
        int p = atomicAdd(&g_cur[d], 1);
        g_pair[p] = make_float2(__int_as_float(s), ew[e]);
    }
}

// ---------------------------------------------------------------------------
// GEMM: hs = dis[row] * (X @ W).  One block = 64 rows, 256 threads, 4x4 tiles.
// EXACT R3 form (scalar sX loads, float4 sW load) — known-good, no reg blowup.
__global__ __launch_bounds__(256) void gemm_hs_kernel(
    const float* __restrict__ Xin, const float* __restrict__ W, int n, int src_sel)
{
    __shared__ float sW[DD * DD];
    __shared__ float sX[DD * DD];

    const float* X = src_sel ? (const float*)g_x1 : Xin;

    int t = threadIdx.x;
    int row0 = blockIdx.x * 64;

    {   // W (4096 floats) coalesced as float4
        float4* sW4 = (float4*)sW;
        const float4* W4 = (const float4*)W;
        #pragma unroll
        for (int i = 0; i < 4; i++) sW4[t + i * 256] = W4[t + i * 256];
    }
    {   // X tile, zero-pad OOB rows
        float4* sX4 = (float4*)sX;
        const float4* X4 = (const float4*)X;
        if (row0 + 64 <= n) {
            #pragma unroll
            for (int i = 0; i < 4; i++) sX4[t + i * 256] = X4[(size_t)row0 * 16 + t + i * 256];
        } else {
            #pragma unroll
            for (int i = 0; i < 4; i++) {
                int idx = t + i * 256;
                int r = idx >> 4;
                float4 v = make_float4(0.f, 0.f, 0.f, 0.f);
                if (row0 + r < n) v = X4[(size_t)row0 * 16 + idx];
                sX4[idx] = v;
            }
        }
    }
    __syncthreads();

    int rg = (t >> 4) * 4;
    int c0 = (t & 15) * 4;

    float a[4][4];
    #pragma unroll
    for (int i = 0; i < 4; i++)
        #pragma unroll
        for (int j = 0; j < 4; j++) a[i][j] = 0.f;

    #pragma unroll 16
    for (int k = 0; k < 64; k++) {
        float4 wv = *(const float4*)(sW + k * 64 + c0);
        #pragma unroll
        for (int i = 0; i < 4; i++) {
            float xv = sX[(rg + i) * 64 + k];
            a[i][0] = fmaf(xv, wv.x, a[i][0]);
            a[i][1] = fmaf(xv, wv.y, a[i][1]);
            a[i][2] = fmaf(xv, wv.z, a[i][2]);
            a[i][3] = fmaf(xv, wv.w, a[i][3]);
        }
    }

    float4* hp = (float4*)g_hs;
    #pragma unroll
    for (int i = 0; i < 4; i++) {
        int r = row0 + rg + i;
        if (r < n) {
            float ds = g_dis[r];
            hp[(size_t)r * 16 + (c0 >> 2)] =
                make_float4(a[i][0] * ds, a[i][1] * ds, a[i][2] * ds, a[i][3] * ds);
        }
    }
}

// ---------------------------------------------------------------------------
// Gather-aggregate: 16 threads per node, thread q owns one float4 column chunk.
// SINGLE DELTA vs R3: edge loop unrolled x2 (two independent LDG.128 in flight).
//   acc = hs[d] (self-loop); acc += w_e * hs[src_e]; r = relu(dis[d]*acc + b)
//   mode 0: x1 = r          mode 1: out = 0.5*(x1 + r)
__global__ __launch_bounds__(256) void gather_kernel(
    const float* __restrict__ b, float* __restrict__ out, int n, int mode)
{
    int gid = blockIdx.x * blockDim.x + threadIdx.x;
    int d = gid >> 4;
    if (d >= n) return;
    int q = gid & 15;

    const float4* __restrict__ hs4 = (const float4*)g_hs;
    size_t oi = (size_t)d * 16 + q;

    float4 acc = hs4[oi];
    int beg = g_row[d];
    int end = g_row[d + 1];

    int i = beg;
    for (; i + 2 <= end; i += 2) {
        float2 p0 = g_pair[i];
        float2 p1 = g_pair[i + 1];
        float4 v0 = hs4[(size_t)__float_as_int(p0.x) * 16 + q];
        float4 v1 = hs4[(size_t)__float_as_int(p1.x) * 16 + q];
        acc.x = fmaf(p0.y, v0.x, acc.x);
        acc.y = fmaf(p0.y, v0.y, acc.y);
        acc.z = fmaf(p0.y, v0.z, acc.z);
        acc.w = fmaf(p0.y, v0.w, acc.w);
        acc.x = fmaf(p1.y, v1.x, acc.x);
        acc.y = fmaf(p1.y, v1.y, acc.y);
        acc.z = fmaf(p1.y, v1.z, acc.z);
        acc.w = fmaf(p1.y, v1.w, acc.w);
    }
    if (i < end) {
        float2 p0 = g_pair[i];
        float4 v0 = hs4[(size_t)__float_as_int(p0.x) * 16 + q];
        acc.x = fmaf(p0.y, v0.x, acc.x);
        acc.y = fmaf(p0.y, v0.y, acc.y);
        acc.z = fmaf(p0.y, v0.z, acc.z);
        acc.w = fmaf(p0.y, v0.w, acc.w);
    }

    float ds = g_dis[d];
    int c = q << 2;
    float4 r;
    r.x = fmaxf(fmaf(ds, acc.x, b[c + 0]), 0.f);
    r.y = fmaxf(fmaf(ds, acc.y, b[c + 1]), 0.f);
    r.z = fmaxf(fmaf(ds, acc.z, b[c + 2]), 0.f);
    r.w = fmaxf(fmaf(ds, acc.w, b[c + 3]), 0.f);

    if (mode == 0) {
        ((float4*)g_x1)[oi] = r;
    } else {
        float4 x1v = ((const float4*)g_x1)[oi];
        r.x = 0.5f * (x1v.x + r.x);
        r.y = 0.5f * (x1v.y + r.y);
        r.z = 0.5f * (x1v.z + r.z);
        r.w = 0.5f * (x1v.w + r.w);
        ((float4*)out)[oi] = r;
    }
}

// ---------------------------------------------------------------------------
extern "C" void kernel_launch(void* const* d_in, const int* in_sizes, int n_in,
                              void* d_out, int out_size) {
    const float* x  = (const float*)d_in[0];
    const int*   ei = (const int*)d_in[1];      // int32 (JAX default x64-disabled)
    const float* ew = (const float*)d_in[2];
    const float* W1 = (const float*)d_in[3];
    const float* b1 = (const float*)d_in[4];
    const float* W2 = (const float*)d_in[5];
    const float* b2 = (const float*)d_in[6];
    float* out = (float*)d_out;

    int n = in_sizes[0] / DD;      // 100000
    int E = in_sizes[2];           // 1200000

    int nb_n   = (n + 255) / 256;
    int nb_e   = (E + 255) / 256;
    int nb_gat = (int)(((long long)n * 16 + 255) / 256);
    int nb_g   = (n + 63) / 64;

    // CSR + degree (shared across both layers) — exact R3 launch order
    init_kernel<<<nb_n, 256>>>(n);
    count_kernel<<<nb_e, 256>>>(ei, ew, E);
    scan_kernel<<<1, 1024>>>(n);
    dis_kernel<<<nb_n, 256>>>(n);
    fill_kernel<<<nb_e, 256>>>(ei, ew, E);

    // Layer 1
    gemm_hs_kernel<<<nb_g, 256>>>(x, W1, n, 0);
    gather_kernel<<<nb_gat, 256>>>(b1, out, n, 0);     // writes g_x1

    // Layer 2
    gemm_hs_kernel<<<nb_g, 256>>>(x, W2, n, 1);        // reads g_x1
    gather_kernel<<<nb_gat, 256>>>(b2, out, n, 1);     // out = 0.5*(x1+x2)
}